// round 11
// baseline (speedup 1.0000x reference)
#include <cuda_runtime.h>
#include <cuda_bf16.h>
#include <cstddef>
#include <cstdint>

// Problem constants
constexpr int kB  = 4;
constexpr int kC  = 512;
constexpr int kN  = 4096;               // 64*64 spatial
constexpr size_t kOutElems = (size_t)kB * kC * kN;      // 8,388,608

// Scratch: pre-split bf16 hi/lo Q and K, K-major [b][n][64]
__device__ __nv_bfloat16 g_qh[(size_t)kB * kN * 64];
__device__ __nv_bfloat16 g_ql[(size_t)kB * kN * 64];
__device__ __nv_bfloat16 g_kh[(size_t)kB * kN * 64];
__device__ __nv_bfloat16 g_kl[(size_t)kB * kN * 64];
__device__ float g_v[(size_t)kB * kC * kN];     // gamma!=0 path only (32 MB)
__device__ float g_vout[(size_t)kB * kC * kN];  // gamma!=0 path only (32 MB)

// ---------------------------------------------------------------------------
// Kernel 1: Q/K projection -> bf16 hi/lo split outputs.
// ---------------------------------------------------------------------------
__global__ __launch_bounds__(256) void proj_qk_kernel(
    const float* __restrict__ y,
    const float* __restrict__ wq, const float* __restrict__ bq,
    const float* __restrict__ wk, const float* __restrict__ bk)
{
    __shared__ __align__(16) float ys[16][64];
    __shared__ __align__(16) float ws[128][16];

    const int b   = blockIdx.y;
    const int n0  = blockIdx.x * 64;
    const int tid = threadIdx.x;
    const int n   = tid & 63;
    const int og  = tid >> 6;

    float acc[32];
#pragma unroll
    for (int j = 0; j < 32; j++) acc[j] = 0.f;

    const float* yb = y + (size_t)b * kC * kN;

    for (int c0 = 0; c0 < kC; c0 += 16) {
#pragma unroll
        for (int k = 0; k < 4; k++) {
            int cc = og + k * 4;
            ys[cc][n] = yb[(size_t)(c0 + cc) * kN + n0 + n];
        }
#pragma unroll
        for (int k = 0; k < 8; k++) {
            int l  = tid + k * 256;
            int o  = l >> 4;
            int cc = l & 15;
            float w = (o < 64) ? wq[o * kC + c0 + cc]
                               : wk[(o - 64) * kC + c0 + cc];
            ws[o][cc] = w;
        }
        __syncthreads();

        float yr[16];
#pragma unroll
        for (int cc = 0; cc < 16; cc++) yr[cc] = ys[cc][n];

#pragma unroll
        for (int j = 0; j < 32; j++) {
            const float4* wr = (const float4*)ws[og * 32 + j];
            float4 w0 = wr[0], w1 = wr[1], w2 = wr[2], w3 = wr[3];
            float s = acc[j];
            s += w0.x * yr[0]  + w0.y * yr[1]  + w0.z * yr[2]  + w0.w * yr[3];
            s += w1.x * yr[4]  + w1.y * yr[5]  + w1.z * yr[6]  + w1.w * yr[7];
            s += w2.x * yr[8]  + w2.y * yr[9]  + w2.z * yr[10] + w2.w * yr[11];
            s += w3.x * yr[12] + w3.y * yr[13] + w3.z * yr[14] + w3.w * yr[15];
            acc[j] = s;
        }
        __syncthreads();
    }

    const size_t rowbase = ((size_t)b * kN + n0 + n) * 64;
#pragma unroll
    for (int j = 0; j < 32; j++) {
        int o = og * 32 + j;
        if (o < 64) {
            float f = acc[j] + bq[o];
            __nv_bfloat16 h = __float2bfloat16(f);
            g_qh[rowbase + o] = h;
            g_ql[rowbase + o] = __float2bfloat16(f - __bfloat162float(h));
        } else {
            float f = acc[j] + bk[o - 64];
            __nv_bfloat16 h = __float2bfloat16(f);
            g_kh[rowbase + (o - 64)] = h;
            g_kl[rowbase + (o - 64)] = __float2bfloat16(f - __bfloat162float(h));
        }
    }
}

// ---------------------------------------------------------------------------
// Kernel 2: FUSED energy+softmax. One block per (m-strip of 128 rows, b).
// Sweep 1: MMA (once!) -> exp -> unnormalized store + reg row-partials.
// Reduce partials (deterministic). Sweep 2 (reverse): RMW strip * rowinv.
// ---------------------------------------------------------------------------
__device__ __forceinline__ void ldm4(uint32_t* r, const __nv_bfloat16* p) {
    uint32_t a = (uint32_t)__cvta_generic_to_shared(p);
    asm volatile("ldmatrix.sync.aligned.m8n8.x4.shared.b16 {%0,%1,%2,%3}, [%4];"
        : "=r"(r[0]), "=r"(r[1]), "=r"(r[2]), "=r"(r[3]) : "r"(a));
}
__device__ __forceinline__ void mma_bf16(float* d, const uint32_t* a, const uint32_t* b) {
    asm volatile(
        "mma.sync.aligned.m16n8k16.row.col.f32.bf16.bf16.f32 "
        "{%0,%1,%2,%3}, {%4,%5,%6,%7}, {%8,%9}, {%0,%1,%2,%3};"
        : "+f"(d[0]), "+f"(d[1]), "+f"(d[2]), "+f"(d[3])
        : "r"(a[0]), "r"(a[1]), "r"(a[2]), "r"(a[3]), "r"(b[0]), "r"(b[1]));
}

constexpr int EPAD = 72;                  // padded row (bf16) for ldmatrix
constexpr int kStgStride = 132;           // fp32 staging stride (528B, 16B-aligned)
constexpr int kTileHalf = 128 * EPAD;     // bf16 elems per tile buffer
// smem: aQ(hi,lo) + bK(hi,lo) + stg + sumbuf(256) + rowinv(128)
constexpr size_t kSmTiles  = (size_t)4 * kTileHalf * sizeof(__nv_bfloat16);   // 73728
constexpr size_t kSmStg    = (size_t)128 * kStgStride * sizeof(float);        // 67584
constexpr size_t kEnergySmem = kSmTiles + kSmStg + (256 + 128) * sizeof(float); // 142848

__global__ __launch_bounds__(256) void energy_fused_kernel(float* __restrict__ attn)
{
    extern __shared__ __nv_bfloat16 sm[];
    __nv_bfloat16* a_hi = sm;
    __nv_bfloat16* a_lo = a_hi + kTileHalf;
    __nv_bfloat16* b_hi = a_lo + kTileHalf;
    __nv_bfloat16* b_lo = b_hi + kTileHalf;
    float* stg    = (float*)(sm + 4 * kTileHalf);
    float* sumbuf = stg + 128 * kStgStride;       // [2][128]
    float* rowinv = sumbuf + 256;                 // [128]

    const int b    = blockIdx.y;
    const int m0   = blockIdx.x * 128;
    const int tid  = threadIdx.x;
    const int lane = tid & 31;
    const int warp = tid >> 5;
    const int wr   = warp >> 1;       // 0..3
    const int wc   = warp & 1;        // 0..1
    const int mwarp = wr * 32;
    const int t8 = lane >> 3, lr = lane & 7;

    // ---- load Q tiles once ----
    {
        const uint4* srcs[2] = {
            (const uint4*)(g_qh + ((size_t)b * kN + m0) * 64),
            (const uint4*)(g_ql + ((size_t)b * kN + m0) * 64) };
        __nv_bfloat16* dsts[2] = { a_hi, a_lo };
#pragma unroll
        for (int t = 0; t < 2; t++) {
#pragma unroll
            for (int i = 0; i < 4; i++) {
                int idx = tid + i * 256;
                int r = idx >> 3, c8 = (idx & 7) * 8;
                *(uint4*)&dsts[t][r * EPAD + c8] = srcs[t][idx];
            }
        }
    }

    float psum[2][2];
#pragma unroll
    for (int i = 0; i < 2; i++)
#pragma unroll
        for (int u = 0; u < 2; u++) psum[i][u] = 0.f;

    float* ab = attn + (size_t)b * kN * kN;

    // ---- sweep 1: all 32 n-tiles ----
    for (int nt = 0; nt < 32; nt++) {
        const int n0 = nt * 128;
        __syncthreads();   // prev MMA reads of bK + prev stg store-reads done
        {
            const uint4* srcs[2] = {
                (const uint4*)(g_kh + ((size_t)b * kN + n0) * 64),
                (const uint4*)(g_kl + ((size_t)b * kN + n0) * 64) };
            __nv_bfloat16* dsts[2] = { b_hi, b_lo };
#pragma unroll
            for (int t = 0; t < 2; t++) {
#pragma unroll
                for (int i = 0; i < 4; i++) {
                    int idx = tid + i * 256;
                    int r = idx >> 3, c8 = (idx & 7) * 8;
                    *(uint4*)&dsts[t][r * EPAD + c8] = srcs[t][idx];
                }
            }
        }
        __syncthreads();

        float acc[2][8][4];
#pragma unroll
        for (int i = 0; i < 2; i++)
#pragma unroll
            for (int j = 0; j < 8; j++)
#pragma unroll
                for (int d = 0; d < 4; d++) acc[i][j][d] = 0.f;

#pragma unroll
        for (int ks = 0; ks < 4; ks++) {
            const int k0 = ks * 16;
            uint32_t ah[2][4], al[2][4];
#pragma unroll
            for (int i = 0; i < 2; i++) {
                const __nv_bfloat16* pa =
                    &a_hi[(mwarp + i * 16 + (t8 & 1) * 8 + lr) * EPAD + k0 + (t8 >> 1) * 8];
                ldm4(ah[i], pa);
                ldm4(al[i], pa + kTileHalf);   // a_lo
            }
#pragma unroll
            for (int jj = 0; jj < 4; jj++) {
                const __nv_bfloat16* pb =
                    &b_hi[(wc * 64 + jj * 16 + (t8 >> 1) * 8 + lr) * EPAD + k0 + (t8 & 1) * 8];
                uint32_t bh[4], bl[4];
                ldm4(bh, pb);
                ldm4(bl, pb + kTileHalf);      // b_lo
#pragma unroll
                for (int i = 0; i < 2; i++) {
#pragma unroll
                    for (int jt = 0; jt < 2; jt++) {
                        float* d = acc[i][jj * 2 + jt];
                        mma_bf16(d, ah[i], bh + 2 * jt);
                        mma_bf16(d, ah[i], bl + 2 * jt);
                        mma_bf16(d, al[i], bh + 2 * jt);
                    }
                }
            }
        }

        // exp -> staging + row partials
        const int rloc = mwarp + (lane >> 2);
        const int cloc = wc * 64 + 2 * (lane & 3);
#pragma unroll
        for (int i = 0; i < 2; i++) {
            const int r = rloc + i * 16;
            float s0 = 0.f, s1 = 0.f;
#pragma unroll
            for (int j = 0; j < 8; j++) {
                const int c = cloc + j * 8;
                float e0 = __expf(acc[i][j][0]);
                float e1 = __expf(acc[i][j][1]);
                float e2 = __expf(acc[i][j][2]);
                float e3 = __expf(acc[i][j][3]);
                stg[(size_t)r * kStgStride + c]           = e0;
                stg[(size_t)r * kStgStride + c + 1]       = e1;
                stg[(size_t)(r + 8) * kStgStride + c]     = e2;
                stg[(size_t)(r + 8) * kStgStride + c + 1] = e3;
                s0 += e0 + e1;
                s1 += e2 + e3;
            }
            psum[i][0] += s0;
            psum[i][1] += s1;
        }
        __syncthreads();

        // unnormalized coalesced store
#pragma unroll
        for (int it = 0; it < 16; it++) {
            int r  = it * 8 + warp;
            int c4 = lane * 4;
            *(float4*)&ab[(size_t)(m0 + r) * kN + n0 + c4] =
                *(const float4*)&stg[r * kStgStride + c4];
        }
    }

    // ---- deterministic rowsum reduction ----
#pragma unroll
    for (int o = 1; o <= 2; o <<= 1) {
#pragma unroll
        for (int i = 0; i < 2; i++)
#pragma unroll
            for (int u = 0; u < 2; u++)
                psum[i][u] += __shfl_xor_sync(0xffffffffu, psum[i][u], o);
    }
    __syncthreads();
    if ((lane & 3) == 0) {
        int rbase = mwarp + (lane >> 2);
#pragma unroll
        for (int i = 0; i < 2; i++)
#pragma unroll
            for (int u = 0; u < 2; u++)
                sumbuf[wc * 128 + rbase + i * 16 + u * 8] = psum[i][u];
    }
    __syncthreads();
    if (tid < 128) rowinv[tid] = 1.0f / (sumbuf[tid] + sumbuf[128 + tid]);
    __syncthreads();

    // ---- sweep 2 (reverse, L2-recency): RMW normalize ----
    for (int nt = 31; nt >= 0; nt--) {
        const int n0 = nt * 128;
#pragma unroll
        for (int it = 0; it < 16; it++) {
            int r  = it * 8 + warp;
            int c4 = lane * 4;
            float inv = rowinv[r];
            float* p = &ab[(size_t)(m0 + r) * kN + n0 + c4];
            float4 v = *(const float4*)p;
            v.x *= inv; v.y *= inv; v.z *= inv; v.w *= inv;
            *(float4*)p = v;
        }
    }
}

// ---------------------------------------------------------------------------
// Kernel 4: V projection (gamma != 0 only).
// ---------------------------------------------------------------------------
__global__ __launch_bounds__(256) void proj_v_kernel(
    const float* __restrict__ x,
    const float* __restrict__ wv, const float* __restrict__ bv,
    const float* __restrict__ gamma)
{
    if (*gamma == 0.0f) return;

    __shared__ __align__(16) float ys[16][64];
    __shared__ __align__(16) float ws[128][16];

    const int b   = blockIdx.z;
    const int ot  = blockIdx.y;
    const int n0  = blockIdx.x * 64;
    const int tid = threadIdx.x;
    const int n   = tid & 63;
    const int og  = tid >> 6;

    float acc[32];
#pragma unroll
    for (int j = 0; j < 32; j++) acc[j] = 0.f;

    const float* xb = x + (size_t)b * kC * kN;
    const float* wbase = wv + (size_t)(ot * 128) * kC;

    for (int c0 = 0; c0 < kC; c0 += 16) {
#pragma unroll
        for (int k = 0; k < 4; k++) {
            int cc = og + k * 4;
            ys[cc][n] = xb[(size_t)(c0 + cc) * kN + n0 + n];
        }
#pragma unroll
        for (int k = 0; k < 8; k++) {
            int l  = tid + k * 256;
            int o  = l >> 4;
            int cc = l & 15;
            ws[o][cc] = wbase[(size_t)o * kC + c0 + cc];
        }
        __syncthreads();

        float yr[16];
#pragma unroll
        for (int cc = 0; cc < 16; cc++) yr[cc] = ys[cc][n];

#pragma unroll
        for (int j = 0; j < 32; j++) {
            const float4* wr = (const float4*)ws[og * 32 + j];
            float4 w0 = wr[0], w1 = wr[1], w2 = wr[2], w3 = wr[3];
            float s = acc[j];
            s += w0.x * yr[0]  + w0.y * yr[1]  + w0.z * yr[2]  + w0.w * yr[3];
            s += w1.x * yr[4]  + w1.y * yr[5]  + w1.z * yr[6]  + w1.w * yr[7];
            s += w2.x * yr[8]  + w2.y * yr[9]  + w2.z * yr[10] + w2.w * yr[11];
            s += w3.x * yr[12] + w3.y * yr[13] + w3.z * yr[14] + w3.w * yr[15];
            acc[j] = s;
        }
        __syncthreads();
    }

    float* vb = g_v + (size_t)b * kC * kN;
#pragma unroll
    for (int j = 0; j < 32; j++) {
        int o = ot * 128 + og * 32 + j;
        vb[(size_t)o * kN + n0 + n] = acc[j] + bv[o];
    }
}

// ---------------------------------------------------------------------------
// Kernel 5: vout = v @ attn^T (gamma != 0 only)
// ---------------------------------------------------------------------------
__global__ __launch_bounds__(256) void bmm_kernel(
    const float* __restrict__ attn, const float* __restrict__ gamma)
{
    if (*gamma == 0.0f) return;

    __shared__ float vS[64][17];
    __shared__ float aS[64][17];

    const int b   = blockIdx.z;
    const int c0  = blockIdx.y * 64;
    const int m0  = blockIdx.x * 64;
    const int tid = threadIdx.x;
    const int tx  = tid & 15;
    const int ty  = tid >> 4;

    float acc[4][4];
#pragma unroll
    for (int i = 0; i < 4; i++)
#pragma unroll
        for (int j = 0; j < 4; j++) acc[i][j] = 0.f;

    const float* vb = g_v + (size_t)b * kC * kN;
    const float* ab = attn + (size_t)b * kN * kN;

    for (int nc = 0; nc < kN; nc += 16) {
#pragma unroll
        for (int k = 0; k < 4; k++) {
            int l = tid + k * 256;
            int r = l >> 4, cc = l & 15;
            vS[r][cc] = vb[(size_t)(c0 + r) * kN + nc + cc];
            aS[r][cc] = ab[(size_t)(m0 + r) * kN + nc + cc];
        }
        __syncthreads();
#pragma unroll
        for (int kk = 0; kk < 16; kk++) {
            float a[4], bb[4];
#pragma unroll
            for (int i = 0; i < 4; i++) a[i]  = vS[ty * 4 + i][kk];
#pragma unroll
            for (int j = 0; j < 4; j++) bb[j] = aS[tx * 4 + j][kk];
#pragma unroll
            for (int i = 0; i < 4; i++)
#pragma unroll
                for (int j = 0; j < 4; j++) acc[i][j] += a[i] * bb[j];
        }
        __syncthreads();
    }

#pragma unroll
    for (int i = 0; i < 4; i++)
#pragma unroll
        for (int j = 0; j < 4; j++)
            g_vout[((size_t)b * kC + c0 + ty * 4 + i) * kN + m0 + tx * 4 + j] = acc[i][j];
}

// ---------------------------------------------------------------------------
// Kernel 6: out = gamma * vout + x  (fast path gamma==0: pure copy)
// ---------------------------------------------------------------------------
__global__ __launch_bounds__(256) void final_kernel(
    const float* __restrict__ x, const float* __restrict__ gamma,
    float* __restrict__ out)
{
    const float g = *gamma;
    const size_t i = ((size_t)blockIdx.x * 256 + threadIdx.x) * 4;
    float4 xv = *(const float4*)&x[i];
    if (g != 0.f) {
        float4 a = *(const float4*)&g_vout[i];
        xv.x += g * a.x; xv.y += g * a.y; xv.z += g * a.z; xv.w += g * a.w;
    }
    *(float4*)&out[i] = xv;
}

// ---------------------------------------------------------------------------
extern "C" void kernel_launch(void* const* d_in, const int* in_sizes, int n_in,
                              void* d_out, int out_size)
{
    const float* x     = (const float*)d_in[0];
    const float* y     = (const float*)d_in[1];
    const float* wq    = (const float*)d_in[2];
    const float* bq    = (const float*)d_in[3];
    const float* wk    = (const float*)d_in[4];
    const float* bk    = (const float*)d_in[5];
    const float* wv    = (const float*)d_in[6];
    const float* bv    = (const float*)d_in[7];
    const float* gamma = (const float*)d_in[8];

    float* out  = (float*)d_out;
    float* attn = out + kOutElems;   // attention output region, [B][N][N]

    cudaFuncSetAttribute(energy_fused_kernel,
                         cudaFuncAttributeMaxDynamicSharedMemorySize,
                         (int)kEnergySmem);

    proj_qk_kernel<<<dim3(kN / 64, kB), 256>>>(y, wq, bq, wk, bk);
    energy_fused_kernel<<<dim3(kN / 128, kB), 256, kEnergySmem>>>(attn);
    proj_v_kernel<<<dim3(kN / 64, 4, kB), 256>>>(x, wv, bv, gamma);
    bmm_kernel<<<dim3(kN / 64, kC / 64, kB), 256>>>(attn, gamma);
    final_kernel<<<(unsigned)(kOutElems / (256 * 4)), 256>>>(x, gamma, out);
}

// round 12
// speedup vs baseline: 1.5777x; 1.5777x over previous
#include <cuda_runtime.h>
#include <cuda_bf16.h>
#include <cstddef>
#include <cstdint>

// Problem constants
constexpr int kB  = 4;
constexpr int kC  = 512;
constexpr int kN  = 4096;               // 64*64 spatial
constexpr size_t kOutElems = (size_t)kB * kC * kN;      // 8,388,608

// Scratch: pre-split bf16 hi/lo Q and K, K-major [b][n][64]
__device__ __nv_bfloat16 g_qh[(size_t)kB * kN * 64];
__device__ __nv_bfloat16 g_ql[(size_t)kB * kN * 64];
__device__ __nv_bfloat16 g_kh[(size_t)kB * kN * 64];
__device__ __nv_bfloat16 g_kl[(size_t)kB * kN * 64];
__device__ float g_partial[(size_t)kB * 32 * kN];   // row-sum partials [b][ntile][m] (8 MB)
__device__ float g_v[(size_t)kB * kC * kN];     // gamma!=0 path only (32 MB)
__device__ float g_vout[(size_t)kB * kC * kN];  // gamma!=0 path only (32 MB)

// ---------------------------------------------------------------------------
// Kernel 1: Q/K projection -> bf16 hi/lo split outputs.
// ---------------------------------------------------------------------------
__global__ __launch_bounds__(256) void proj_qk_kernel(
    const float* __restrict__ y,
    const float* __restrict__ wq, const float* __restrict__ bq,
    const float* __restrict__ wk, const float* __restrict__ bk)
{
    __shared__ __align__(16) float ys[16][64];
    __shared__ __align__(16) float ws[128][16];

    const int b   = blockIdx.y;
    const int n0  = blockIdx.x * 64;
    const int tid = threadIdx.x;
    const int n   = tid & 63;
    const int og  = tid >> 6;

    float acc[32];
#pragma unroll
    for (int j = 0; j < 32; j++) acc[j] = 0.f;

    const float* yb = y + (size_t)b * kC * kN;

    for (int c0 = 0; c0 < kC; c0 += 16) {
#pragma unroll
        for (int k = 0; k < 4; k++) {
            int cc = og + k * 4;
            ys[cc][n] = yb[(size_t)(c0 + cc) * kN + n0 + n];
        }
#pragma unroll
        for (int k = 0; k < 8; k++) {
            int l  = tid + k * 256;
            int o  = l >> 4;
            int cc = l & 15;
            float w = (o < 64) ? wq[o * kC + c0 + cc]
                               : wk[(o - 64) * kC + c0 + cc];
            ws[o][cc] = w;
        }
        __syncthreads();

        float yr[16];
#pragma unroll
        for (int cc = 0; cc < 16; cc++) yr[cc] = ys[cc][n];

#pragma unroll
        for (int j = 0; j < 32; j++) {
            const float4* wr = (const float4*)ws[og * 32 + j];
            float4 w0 = wr[0], w1 = wr[1], w2 = wr[2], w3 = wr[3];
            float s = acc[j];
            s += w0.x * yr[0]  + w0.y * yr[1]  + w0.z * yr[2]  + w0.w * yr[3];
            s += w1.x * yr[4]  + w1.y * yr[5]  + w1.z * yr[6]  + w1.w * yr[7];
            s += w2.x * yr[8]  + w2.y * yr[9]  + w2.z * yr[10] + w2.w * yr[11];
            s += w3.x * yr[12] + w3.y * yr[13] + w3.z * yr[14] + w3.w * yr[15];
            acc[j] = s;
        }
        __syncthreads();
    }

    const size_t rowbase = ((size_t)b * kN + n0 + n) * 64;
#pragma unroll
    for (int j = 0; j < 32; j++) {
        int o = og * 32 + j;
        if (o < 64) {
            float f = acc[j] + bq[o];
            __nv_bfloat16 h = __float2bfloat16(f);
            g_qh[rowbase + o] = h;
            g_ql[rowbase + o] = __float2bfloat16(f - __bfloat162float(h));
        } else {
            float f = acc[j] + bk[o - 64];
            __nv_bfloat16 h = __float2bfloat16(f);
            g_kh[rowbase + (o - 64)] = h;
            g_kl[rowbase + (o - 64)] = __float2bfloat16(f - __bfloat162float(h));
        }
    }
}

// ---------------------------------------------------------------------------
// Kernel 2: energy via bf16 mma.sync (3-product split), SINGLE pass.
// Stores unnormalized exp(S) + per-tile row partial sums (from registers).
// Grid (32, 32, B) -> 4096 CTAs, 2 CTAs/SM: proven-good overlap.
// ---------------------------------------------------------------------------
__device__ __forceinline__ void ldm4(uint32_t* r, const __nv_bfloat16* p) {
    uint32_t a = (uint32_t)__cvta_generic_to_shared(p);
    asm volatile("ldmatrix.sync.aligned.m8n8.x4.shared.b16 {%0,%1,%2,%3}, [%4];"
        : "=r"(r[0]), "=r"(r[1]), "=r"(r[2]), "=r"(r[3]) : "r"(a));
}
__device__ __forceinline__ void mma_bf16(float* d, const uint32_t* a, const uint32_t* b) {
    asm volatile(
        "mma.sync.aligned.m16n8k16.row.col.f32.bf16.bf16.f32 "
        "{%0,%1,%2,%3}, {%4,%5,%6,%7}, {%8,%9}, {%0,%1,%2,%3};"
        : "+f"(d[0]), "+f"(d[1]), "+f"(d[2]), "+f"(d[3])
        : "r"(a[0]), "r"(a[1]), "r"(a[2]), "r"(a[3]), "r"(b[0]), "r"(b[1]));
}

constexpr int EPAD = 72;                       // padded row (bf16) for ldmatrix
constexpr int kStgStride = 132;                // fp32 staging stride (528B, 16B-aligned)
constexpr size_t kEnergySmem = (size_t)4 * 128 * EPAD * sizeof(__nv_bfloat16); // 73728
// staging reuse: 128*132*4 + sumbuf 256*4 + pad = 69120 <= 73728  OK

__global__ __launch_bounds__(256) void energy_kernel(float* __restrict__ attn)
{
    extern __shared__ __nv_bfloat16 sm[];
    __nv_bfloat16* a_hi = sm;
    __nv_bfloat16* a_lo = a_hi + 128 * EPAD;
    __nv_bfloat16* b_hi = a_lo + 128 * EPAD;
    __nv_bfloat16* b_lo = b_hi + 128 * EPAD;

    const int b    = blockIdx.z;
    const int m0   = blockIdx.y * 128;
    const int n0   = blockIdx.x * 128;
    const int tid  = threadIdx.x;
    const int lane = tid & 31;
    const int warp = tid >> 5;
    const int wr   = warp >> 1;       // 0..3
    const int wc   = warp & 1;        // 0..1
    const int mwarp = wr * 32;

    // ---- copy pre-split bf16 tiles into padded smem ----
    {
        const __nv_bfloat16* srcs[4] = {
            g_qh + ((size_t)b * kN + m0) * 64,
            g_ql + ((size_t)b * kN + m0) * 64,
            g_kh + ((size_t)b * kN + n0) * 64,
            g_kl + ((size_t)b * kN + n0) * 64 };
        __nv_bfloat16* dsts[4] = { a_hi, a_lo, b_hi, b_lo };
#pragma unroll
        for (int t = 0; t < 4; t++) {
            const uint4* src = (const uint4*)srcs[t];
            __nv_bfloat16* dst = dsts[t];
#pragma unroll
            for (int i = 0; i < 4; i++) {
                int idx = tid + i * 256;          // uint4 index, 0..1023
                int r = idx >> 3, c8 = (idx & 7) * 8;
                *(uint4*)&dst[r * EPAD + c8] = src[idx];
            }
        }
    }
    __syncthreads();

    float acc[2][8][4];
#pragma unroll
    for (int i = 0; i < 2; i++)
#pragma unroll
        for (int j = 0; j < 8; j++)
#pragma unroll
            for (int d = 0; d < 4; d++) acc[i][j][d] = 0.f;

    const int t8 = lane >> 3, lr = lane & 7;

#pragma unroll
    for (int ks = 0; ks < 4; ks++) {
        const int k0 = ks * 16;
        uint32_t ah[2][4], al[2][4];
#pragma unroll
        for (int i = 0; i < 2; i++) {
            const __nv_bfloat16* pa =
                &a_hi[(mwarp + i * 16 + (t8 & 1) * 8 + lr) * EPAD + k0 + (t8 >> 1) * 8];
            ldm4(ah[i], pa);
            ldm4(al[i], pa + 128 * EPAD);   // a_lo
        }
#pragma unroll
        for (int jj = 0; jj < 4; jj++) {
            const __nv_bfloat16* pb =
                &b_hi[(wc * 64 + jj * 16 + (t8 >> 1) * 8 + lr) * EPAD + k0 + (t8 & 1) * 8];
            uint32_t bh[4], bl[4];
            ldm4(bh, pb);
            ldm4(bl, pb + 128 * EPAD);      // b_lo
#pragma unroll
            for (int i = 0; i < 2; i++) {
#pragma unroll
                for (int jt = 0; jt < 2; jt++) {
                    float* d = acc[i][jj * 2 + jt];
                    mma_bf16(d, ah[i], bh + 2 * jt);
                    mma_bf16(d, ah[i], bl + 2 * jt);
                    mma_bf16(d, al[i], bh + 2 * jt);
                }
            }
        }
    }

    __syncthreads();   // tiles consumed; reuse smem as fp32 staging

    float* stg    = (float*)sm;                  // 128 x 132 floats = 67584 B
    float* sumbuf = stg + 128 * kStgStride;      // [2][128] floats

    // ---- exp -> staging + per-thread row partials ----
    const int rloc = mwarp + (lane >> 2);
    const int cloc = wc * 64 + 2 * (lane & 3);
    float psum[2][2];
#pragma unroll
    for (int i = 0; i < 2; i++) {
        const int r = rloc + i * 16;
        float s0 = 0.f, s1 = 0.f;
#pragma unroll
        for (int j = 0; j < 8; j++) {
            const int c = cloc + j * 8;
            float e0 = __expf(acc[i][j][0]);
            float e1 = __expf(acc[i][j][1]);
            float e2 = __expf(acc[i][j][2]);
            float e3 = __expf(acc[i][j][3]);
            stg[(size_t)r * kStgStride + c]           = e0;
            stg[(size_t)r * kStgStride + c + 1]       = e1;
            stg[(size_t)(r + 8) * kStgStride + c]     = e2;
            stg[(size_t)(r + 8) * kStgStride + c + 1] = e3;
            s0 += e0 + e1;
            s1 += e2 + e3;
        }
        psum[i][0] = s0;
        psum[i][1] = s1;
    }
    // reduce over the 4 lanes sharing each row
#pragma unroll
    for (int o = 1; o <= 2; o <<= 1) {
#pragma unroll
        for (int i = 0; i < 2; i++)
#pragma unroll
            for (int u = 0; u < 2; u++)
                psum[i][u] += __shfl_xor_sync(0xffffffffu, psum[i][u], o);
    }
    if ((lane & 3) == 0) {
        int rbase = mwarp + (lane >> 2);
#pragma unroll
        for (int i = 0; i < 2; i++)
#pragma unroll
            for (int u = 0; u < 2; u++)
                sumbuf[wc * 128 + rbase + i * 16 + u * 8] = psum[i][u];
    }
    __syncthreads();

    if (tid < 128) {
        g_partial[((size_t)b * 32 + blockIdx.x) * kN + m0 + tid] =
            sumbuf[tid] + sumbuf[128 + tid];
    }

    // ---- unnormalized coalesced store ----
    float* ab = attn + (size_t)b * kN * kN;
#pragma unroll
    for (int it = 0; it < 16; it++) {
        int r  = it * 8 + warp;
        int c4 = lane * 4;
        *(float4*)&ab[(size_t)(m0 + r) * kN + n0 + c4] =
            *(const float4*)&stg[r * kStgStride + c4];
    }
}

// ---------------------------------------------------------------------------
// Kernel 3: normalize rows using precomputed partials. One block per row.
// ---------------------------------------------------------------------------
__global__ __launch_bounds__(256) void normalize_kernel(float* __restrict__ attn)
{
    __shared__ float s_inv;
    const int row = blockIdx.x;           // b*kN + m
    const int b   = row >> 12;
    const int m   = row & (kN - 1);
    const int tid = threadIdx.x;

    if (tid < 32) {
        float s = g_partial[((size_t)b * 32 + tid) * kN + m];
#pragma unroll
        for (int o = 16; o > 0; o >>= 1) s += __shfl_xor_sync(0xffffffffu, s, o);
        if (tid == 0) s_inv = 1.0f / s;
    }
    __syncthreads();
    const float inv = s_inv;

    float4* p = (float4*)(attn + (size_t)row * kN);
#pragma unroll
    for (int i = 0; i < 4; i++) {
        float4 v = p[tid + i * 256];
        v.x *= inv; v.y *= inv; v.z *= inv; v.w *= inv;
        p[tid + i * 256] = v;
    }
}

// ---------------------------------------------------------------------------
// Kernel 4: V projection (gamma != 0 only).
// ---------------------------------------------------------------------------
__global__ __launch_bounds__(256) void proj_v_kernel(
    const float* __restrict__ x,
    const float* __restrict__ wv, const float* __restrict__ bv,
    const float* __restrict__ gamma)
{
    if (*gamma == 0.0f) return;

    __shared__ __align__(16) float ys[16][64];
    __shared__ __align__(16) float ws[128][16];

    const int b   = blockIdx.z;
    const int ot  = blockIdx.y;
    const int n0  = blockIdx.x * 64;
    const int tid = threadIdx.x;
    const int n   = tid & 63;
    const int og  = tid >> 6;

    float acc[32];
#pragma unroll
    for (int j = 0; j < 32; j++) acc[j] = 0.f;

    const float* xb = x + (size_t)b * kC * kN;
    const float* wbase = wv + (size_t)(ot * 128) * kC;

    for (int c0 = 0; c0 < kC; c0 += 16) {
#pragma unroll
        for (int k = 0; k < 4; k++) {
            int cc = og + k * 4;
            ys[cc][n] = xb[(size_t)(c0 + cc) * kN + n0 + n];
        }
#pragma unroll
        for (int k = 0; k < 8; k++) {
            int l  = tid + k * 256;
            int o  = l >> 4;
            int cc = l & 15;
            ws[o][cc] = wbase[(size_t)o * kC + c0 + cc];
        }
        __syncthreads();

        float yr[16];
#pragma unroll
        for (int cc = 0; cc < 16; cc++) yr[cc] = ys[cc][n];

#pragma unroll
        for (int j = 0; j < 32; j++) {
            const float4* wr = (const float4*)ws[og * 32 + j];
            float4 w0 = wr[0], w1 = wr[1], w2 = wr[2], w3 = wr[3];
            float s = acc[j];
            s += w0.x * yr[0]  + w0.y * yr[1]  + w0.z * yr[2]  + w0.w * yr[3];
            s += w1.x * yr[4]  + w1.y * yr[5]  + w1.z * yr[6]  + w1.w * yr[7];
            s += w2.x * yr[8]  + w2.y * yr[9]  + w2.z * yr[10] + w2.w * yr[11];
            s += w3.x * yr[12] + w3.y * yr[13] + w3.z * yr[14] + w3.w * yr[15];
            acc[j] = s;
        }
        __syncthreads();
    }

    float* vb = g_v + (size_t)b * kC * kN;
#pragma unroll
    for (int j = 0; j < 32; j++) {
        int o = ot * 128 + og * 32 + j;
        vb[(size_t)o * kN + n0 + n] = acc[j] + bv[o];
    }
}

// ---------------------------------------------------------------------------
// Kernel 5: vout = v @ attn^T (gamma != 0 only)
// ---------------------------------------------------------------------------
__global__ __launch_bounds__(256) void bmm_kernel(
    const float* __restrict__ attn, const float* __restrict__ gamma)
{
    if (*gamma == 0.0f) return;

    __shared__ float vS[64][17];
    __shared__ float aS[64][17];

    const int b   = blockIdx.z;
    const int c0  = blockIdx.y * 64;
    const int m0  = blockIdx.x * 64;
    const int tid = threadIdx.x;
    const int tx  = tid & 15;
    const int ty  = tid >> 4;

    float acc[4][4];
#pragma unroll
    for (int i = 0; i < 4; i++)
#pragma unroll
        for (int j = 0; j < 4; j++) acc[i][j] = 0.f;

    const float* vb = g_v + (size_t)b * kC * kN;
    const float* ab = attn + (size_t)b * kN * kN;

    for (int nc = 0; nc < kN; nc += 16) {
#pragma unroll
        for (int k = 0; k < 4; k++) {
            int l = tid + k * 256;
            int r = l >> 4, cc = l & 15;
            vS[r][cc] = vb[(size_t)(c0 + r) * kN + nc + cc];
            aS[r][cc] = ab[(size_t)(m0 + r) * kN + nc + cc];
        }
        __syncthreads();
#pragma unroll
        for (int kk = 0; kk < 16; kk++) {
            float a[4], bb[4];
#pragma unroll
            for (int i = 0; i < 4; i++) a[i]  = vS[ty * 4 + i][kk];
#pragma unroll
            for (int j = 0; j < 4; j++) bb[j] = aS[tx * 4 + j][kk];
#pragma unroll
            for (int i = 0; i < 4; i++)
#pragma unroll
                for (int j = 0; j < 4; j++) acc[i][j] += a[i] * bb[j];
        }
        __syncthreads();
    }

#pragma unroll
    for (int i = 0; i < 4; i++)
#pragma unroll
        for (int j = 0; j < 4; j++)
            g_vout[((size_t)b * kC + c0 + ty * 4 + i) * kN + m0 + tx * 4 + j] = acc[i][j];
}

// ---------------------------------------------------------------------------
// Kernel 6: out = gamma * vout + x  (fast path gamma==0: pure copy)
// ---------------------------------------------------------------------------
__global__ __launch_bounds__(256) void final_kernel(
    const float* __restrict__ x, const float* __restrict__ gamma,
    float* __restrict__ out)
{
    const float g = *gamma;
    const size_t i = ((size_t)blockIdx.x * 256 + threadIdx.x) * 4;
    float4 xv = *(const float4*)&x[i];
    if (g != 0.f) {
        float4 a = *(const float4*)&g_vout[i];
        xv.x += g * a.x; xv.y += g * a.y; xv.z += g * a.z; xv.w += g * a.w;
    }
    *(float4*)&out[i] = xv;
}

// ---------------------------------------------------------------------------
extern "C" void kernel_launch(void* const* d_in, const int* in_sizes, int n_in,
                              void* d_out, int out_size)
{
    const float* x     = (const float*)d_in[0];
    const float* y     = (const float*)d_in[1];
    const float* wq    = (const float*)d_in[2];
    const float* bq    = (const float*)d_in[3];
    const float* wk    = (const float*)d_in[4];
    const float* bk    = (const float*)d_in[5];
    const float* wv    = (const float*)d_in[6];
    const float* bv    = (const float*)d_in[7];
    const float* gamma = (const float*)d_in[8];

    float* out  = (float*)d_out;
    float* attn = out + kOutElems;   // attention output region, [B][N][N]

    cudaFuncSetAttribute(energy_kernel,
                         cudaFuncAttributeMaxDynamicSharedMemorySize,
                         (int)kEnergySmem);

    proj_qk_kernel<<<dim3(kN / 64, kB), 256>>>(y, wq, bq, wk, bk);
    energy_kernel<<<dim3(kN / 128, kN / 128, kB), 256, kEnergySmem>>>(attn);
    normalize_kernel<<<kB * kN, 256>>>(attn);
    proj_v_kernel<<<dim3(kN / 64, 4, kB), 256>>>(x, wv, bv, gamma);
    bmm_kernel<<<dim3(kN / 64, kC / 64, kB), 256>>>(attn, gamma);
    final_kernel<<<(unsigned)(kOutElems / (256 * 4)), 256>>>(x, gamma, out);
}

// round 13
// speedup vs baseline: 2.0443x; 1.2958x over previous
#include <cuda_runtime.h>
#include <cuda_bf16.h>
#include <cstddef>
#include <cstdint>

// Problem constants
constexpr int kB  = 4;
constexpr int kC  = 512;
constexpr int kN  = 4096;               // 64*64 spatial
constexpr size_t kOutElems = (size_t)kB * kC * kN;      // 8,388,608

// Scratch: pre-split bf16 hi/lo Q and K, K-major [b][n][64]
__device__ __nv_bfloat16 g_qh[(size_t)kB * kN * 64];
__device__ __nv_bfloat16 g_ql[(size_t)kB * kN * 64];
__device__ __nv_bfloat16 g_kh[(size_t)kB * kN * 64];
__device__ __nv_bfloat16 g_kl[(size_t)kB * kN * 64];
__device__ float g_partial[(size_t)kB * 32 * kN];   // row-sum partials [b][ntile][m] (8 MB)
__device__ float g_v[(size_t)kB * kC * kN];     // gamma!=0 path only (32 MB)
__device__ float g_vout[(size_t)kB * kC * kN];  // gamma!=0 path only (32 MB)

// ---------------------------------------------------------------------------
// Shared PTX helpers
// ---------------------------------------------------------------------------
__device__ __forceinline__ void ldm4(uint32_t* r, const __nv_bfloat16* p) {
    uint32_t a = (uint32_t)__cvta_generic_to_shared(p);
    asm volatile("ldmatrix.sync.aligned.m8n8.x4.shared.b16 {%0,%1,%2,%3}, [%4];"
        : "=r"(r[0]), "=r"(r[1]), "=r"(r[2]), "=r"(r[3]) : "r"(a));
}
__device__ __forceinline__ void mma_bf16(float* d, const uint32_t* a, const uint32_t* b) {
    asm volatile(
        "mma.sync.aligned.m16n8k16.row.col.f32.bf16.bf16.f32 "
        "{%0,%1,%2,%3}, {%4,%5,%6,%7}, {%8,%9}, {%0,%1,%2,%3};"
        : "+f"(d[0]), "+f"(d[1]), "+f"(d[2]), "+f"(d[3])
        : "r"(a[0]), "r"(a[1]), "r"(a[2]), "r"(a[3]), "r"(b[0]), "r"(b[1]));
}

// ---------------------------------------------------------------------------
// Kernel 1: Q/K projection via bf16 tensor cores (3-product split).
// GEMM: out[o in 0..128][n] = sum_c w[o][c] * y[b][c][n] + bias
// Tile: M=128 (all outputs), N=64 positions, K=512 in k16 chunks, dbl-buffered.
// Epilogue: bias + hi/lo bf16 split + transpose-store to g_q*/g_k* [n][64].
// ---------------------------------------------------------------------------
constexpr int PPAD = 24;   // bf16 row stride (48B, 16B-aligned) for ldmatrix tiles
// smem layout (bytes): A_HI[2]@0 (2*6144), A_LO[2]@12288, B_HI[2]@24576 (2*3072),
//                      B_LO[2]@30720. total 36864. Epilogue stg 128x68 fp32 = 34816 (alias).
constexpr size_t kProjSmem = 36864;

__global__ __launch_bounds__(256) void proj_qk_tc_kernel(
    const float* __restrict__ y,
    const float* __restrict__ wq, const float* __restrict__ bq,
    const float* __restrict__ wk, const float* __restrict__ bk)
{
    extern __shared__ char psm[];
    const int b   = blockIdx.y;
    const int n0  = blockIdx.x * 64;
    const int tid = threadIdx.x;
    const int lane = tid & 31;
    const int warp = tid >> 5;
    const int wr   = warp >> 1;       // 0..3 : o-rows of 32
    const int wc   = warp & 1;        // 0..1 : n-cols of 32
    const int t8 = lane >> 3, lr = lane & 7;

    auto a_hi = [&](int buf) { return (__nv_bfloat16*)(psm + buf * 6144); };
    auto a_lo = [&](int buf) { return (__nv_bfloat16*)(psm + 12288 + buf * 6144); };
    auto b_hi = [&](int buf) { return (__nv_bfloat16*)(psm + 24576 + buf * 3072); };
    auto b_lo = [&](int buf) { return (__nv_bfloat16*)(psm + 30720 + buf * 3072); };

    const float* yb = y + (size_t)b * kC * kN;

    // per-thread load assignments (fixed across chunks)
    const int yc  = tid >> 4;            // 0..15 channel within chunk
    const int yn4 = (tid & 15) * 4;      // n offset (float4)
    const int wo0 = (tid * 2) >> 2;      // two w float4s: idx = 2*tid, 2*tid+1
    const int wc40 = ((tid * 2) & 3) * 4;
    const int wo1 = (tid * 2 + 1) >> 2;
    const int wc41 = ((tid * 2 + 1) & 3) * 4;

    float4 yv, wv0, wv1;

    auto load_regs = [&](int ck) {
        const int c0 = ck * 16;
        yv = *(const float4*)&yb[(size_t)(c0 + yc) * kN + n0 + yn4];
        wv0 = (wo0 < 64) ? *(const float4*)&wq[wo0 * kC + c0 + wc40]
                         : *(const float4*)&wk[(wo0 - 64) * kC + c0 + wc40];
        wv1 = (wo1 < 64) ? *(const float4*)&wq[wo1 * kC + c0 + wc41]
                         : *(const float4*)&wk[(wo1 - 64) * kC + c0 + wc41];
    };
    auto store_buf = [&](int buf) {
        __nv_bfloat16* ah = a_hi(buf); __nv_bfloat16* al = a_lo(buf);
        __nv_bfloat16* bh = b_hi(buf); __nv_bfloat16* bl = b_lo(buf);
        float yf[4] = {yv.x, yv.y, yv.z, yv.w};
#pragma unroll
        for (int d = 0; d < 4; d++) {
            __nv_bfloat16 h = __float2bfloat16(yf[d]);
            bh[(yn4 + d) * PPAD + yc] = h;
            bl[(yn4 + d) * PPAD + yc] = __float2bfloat16(yf[d] - __bfloat162float(h));
        }
        float wf0[4] = {wv0.x, wv0.y, wv0.z, wv0.w};
        float wf1[4] = {wv1.x, wv1.y, wv1.z, wv1.w};
#pragma unroll
        for (int d = 0; d < 4; d++) {
            __nv_bfloat16 h0 = __float2bfloat16(wf0[d]);
            ah[wo0 * PPAD + wc40 + d] = h0;
            al[wo0 * PPAD + wc40 + d] = __float2bfloat16(wf0[d] - __bfloat162float(h0));
            __nv_bfloat16 h1 = __float2bfloat16(wf1[d]);
            ah[wo1 * PPAD + wc41 + d] = h1;
            al[wo1 * PPAD + wc41 + d] = __float2bfloat16(wf1[d] - __bfloat162float(h1));
        }
    };

    float acc[2][4][4];
#pragma unroll
    for (int i = 0; i < 2; i++)
#pragma unroll
        for (int j = 0; j < 4; j++)
#pragma unroll
            for (int d = 0; d < 4; d++) acc[i][j][d] = 0.f;

    load_regs(0);
    store_buf(0);
    __syncthreads();

    for (int ck = 0; ck < 32; ck++) {
        if (ck < 31) load_regs(ck + 1);

        const int buf = ck & 1;
        const __nv_bfloat16* ahp = a_hi(buf);
        const __nv_bfloat16* bhp = b_hi(buf);
        uint32_t ah[2][4], al[2][4];
#pragma unroll
        for (int i = 0; i < 2; i++) {
            const __nv_bfloat16* pa =
                &ahp[(wr * 32 + i * 16 + (t8 & 1) * 8 + lr) * PPAD + (t8 >> 1) * 8];
            ldm4(ah[i], pa);
            ldm4(al[i], pa + (12288 / 2));   // a_lo at +12288 bytes from a_hi(buf)
        }
#pragma unroll
        for (int jj = 0; jj < 2; jj++) {
            const __nv_bfloat16* pb =
                &bhp[(wc * 32 + jj * 16 + (t8 >> 1) * 8 + lr) * PPAD + (t8 & 1) * 8];
            uint32_t bh[4], bl[4];
            ldm4(bh, pb);
            ldm4(bl, pb + (6144 / 2));       // b_lo at +6144 bytes from b_hi(buf)
#pragma unroll
            for (int i = 0; i < 2; i++) {
#pragma unroll
                for (int jt = 0; jt < 2; jt++) {
                    float* d = acc[i][jj * 2 + jt];
                    mma_bf16(d, ah[i], bh + 2 * jt);
                    mma_bf16(d, ah[i], bl + 2 * jt);
                    mma_bf16(d, al[i], bh + 2 * jt);
                }
            }
        }

        if (ck < 31) store_buf((ck + 1) & 1);
        __syncthreads();
    }

    // ---- epilogue: bias + stage fp32 [o][n] ----
    float* stg = (float*)psm;    // 128 x 68
    const int rloc = wr * 32 + (lane >> 2);
    const int cloc = wc * 32 + 2 * (lane & 3);
#pragma unroll
    for (int i = 0; i < 2; i++) {
        const int r = rloc + i * 16;
        const float bias0 = (r < 64)     ? bq[r]      : bk[r - 64];
        const float bias1 = (r + 8 < 64) ? bq[r + 8]  : bk[r + 8 - 64];
#pragma unroll
        for (int j = 0; j < 4; j++) {
            const int c = cloc + j * 8;
            stg[r * 68 + c]           = acc[i][j][0] + bias0;
            stg[r * 68 + c + 1]       = acc[i][j][1] + bias0;
            stg[(r + 8) * 68 + c]     = acc[i][j][2] + bias1;
            stg[(r + 8) * 68 + c + 1] = acc[i][j][3] + bias1;
        }
    }
    __syncthreads();

    // ---- transposed split stores: [n][64] K-major, coalesced 8B per thread ----
    // thread t: n = t/16 (+16 per pass), og = (t%16)*4
    const int tn  = tid >> 4;            // 0..15
    const int tog = (tid & 15) * 4;      // 0..60
#pragma unroll
    for (int p = 0; p < 4; p++) {
        const int n = tn + p * 16;
        const size_t rowq = ((size_t)b * kN + n0 + n) * 64 + tog;
        // q part (o = tog..tog+3)
        {
            __nv_bfloat16 h[4], l[4];
#pragma unroll
            for (int d = 0; d < 4; d++) {
                float f = stg[(tog + d) * 68 + n];
                h[d] = __float2bfloat16(f);
                l[d] = __float2bfloat16(f - __bfloat162float(h[d]));
            }
            *(uint2*)&g_qh[rowq] = *(const uint2*)h;
            *(uint2*)&g_ql[rowq] = *(const uint2*)l;
        }
        // k part (o = 64+tog .. 64+tog+3)
        {
            __nv_bfloat16 h[4], l[4];
#pragma unroll
            for (int d = 0; d < 4; d++) {
                float f = stg[(64 + tog + d) * 68 + n];
                h[d] = __float2bfloat16(f);
                l[d] = __float2bfloat16(f - __bfloat162float(h[d]));
            }
            *(uint2*)&g_kh[rowq] = *(const uint2*)h;
            *(uint2*)&g_kl[rowq] = *(const uint2*)l;
        }
    }
}

// ---------------------------------------------------------------------------
// Kernel 2: energy via bf16 mma.sync (3-product split), SINGLE pass.
// Stores unnormalized exp(S) + per-tile row partial sums (from registers).
// ---------------------------------------------------------------------------
constexpr int EPAD = 72;                       // padded row (bf16) for ldmatrix
constexpr int kStgStride = 132;                // fp32 staging stride (528B, 16B-aligned)
constexpr size_t kEnergySmem = (size_t)4 * 128 * EPAD * sizeof(__nv_bfloat16); // 73728

__global__ __launch_bounds__(256) void energy_kernel(float* __restrict__ attn)
{
    extern __shared__ __nv_bfloat16 sm[];
    __nv_bfloat16* a_hi = sm;
    __nv_bfloat16* a_lo = a_hi + 128 * EPAD;
    __nv_bfloat16* b_hi = a_lo + 128 * EPAD;
    __nv_bfloat16* b_lo = b_hi + 128 * EPAD;

    const int b    = blockIdx.z;
    const int m0   = blockIdx.y * 128;
    const int n0   = blockIdx.x * 128;
    const int tid  = threadIdx.x;
    const int lane = tid & 31;
    const int warp = tid >> 5;
    const int wr   = warp >> 1;
    const int wc   = warp & 1;
    const int mwarp = wr * 32;

    {
        const __nv_bfloat16* srcs[4] = {
            g_qh + ((size_t)b * kN + m0) * 64,
            g_ql + ((size_t)b * kN + m0) * 64,
            g_kh + ((size_t)b * kN + n0) * 64,
            g_kl + ((size_t)b * kN + n0) * 64 };
        __nv_bfloat16* dsts[4] = { a_hi, a_lo, b_hi, b_lo };
#pragma unroll
        for (int t = 0; t < 4; t++) {
            const uint4* src = (const uint4*)srcs[t];
            __nv_bfloat16* dst = dsts[t];
#pragma unroll
            for (int i = 0; i < 4; i++) {
                int idx = tid + i * 256;
                int r = idx >> 3, c8 = (idx & 7) * 8;
                *(uint4*)&dst[r * EPAD + c8] = src[idx];
            }
        }
    }
    __syncthreads();

    float acc[2][8][4];
#pragma unroll
    for (int i = 0; i < 2; i++)
#pragma unroll
        for (int j = 0; j < 8; j++)
#pragma unroll
            for (int d = 0; d < 4; d++) acc[i][j][d] = 0.f;

    const int t8 = lane >> 3, lr = lane & 7;

#pragma unroll
    for (int ks = 0; ks < 4; ks++) {
        const int k0 = ks * 16;
        uint32_t ah[2][4], al[2][4];
#pragma unroll
        for (int i = 0; i < 2; i++) {
            const __nv_bfloat16* pa =
                &a_hi[(mwarp + i * 16 + (t8 & 1) * 8 + lr) * EPAD + k0 + (t8 >> 1) * 8];
            ldm4(ah[i], pa);
            ldm4(al[i], pa + 128 * EPAD);
        }
#pragma unroll
        for (int jj = 0; jj < 4; jj++) {
            const __nv_bfloat16* pb =
                &b_hi[(wc * 64 + jj * 16 + (t8 >> 1) * 8 + lr) * EPAD + k0 + (t8 & 1) * 8];
            uint32_t bh[4], bl[4];
            ldm4(bh, pb);
            ldm4(bl, pb + 128 * EPAD);
#pragma unroll
            for (int i = 0; i < 2; i++) {
#pragma unroll
                for (int jt = 0; jt < 2; jt++) {
                    float* d = acc[i][jj * 2 + jt];
                    mma_bf16(d, ah[i], bh + 2 * jt);
                    mma_bf16(d, ah[i], bl + 2 * jt);
                    mma_bf16(d, al[i], bh + 2 * jt);
                }
            }
        }
    }

    __syncthreads();

    float* stg    = (float*)sm;
    float* sumbuf = stg + 128 * kStgStride;

    const int rloc = mwarp + (lane >> 2);
    const int cloc = wc * 64 + 2 * (lane & 3);
    float psum[2][2];
#pragma unroll
    for (int i = 0; i < 2; i++) {
        const int r = rloc + i * 16;
        float s0 = 0.f, s1 = 0.f;
#pragma unroll
        for (int j = 0; j < 8; j++) {
            const int c = cloc + j * 8;
            float e0 = __expf(acc[i][j][0]);
            float e1 = __expf(acc[i][j][1]);
            float e2 = __expf(acc[i][j][2]);
            float e3 = __expf(acc[i][j][3]);
            stg[(size_t)r * kStgStride + c]           = e0;
            stg[(size_t)r * kStgStride + c + 1]       = e1;
            stg[(size_t)(r + 8) * kStgStride + c]     = e2;
            stg[(size_t)(r + 8) * kStgStride + c + 1] = e3;
            s0 += e0 + e1;
            s1 += e2 + e3;
        }
        psum[i][0] = s0;
        psum[i][1] = s1;
    }
#pragma unroll
    for (int o = 1; o <= 2; o <<= 1) {
#pragma unroll
        for (int i = 0; i < 2; i++)
#pragma unroll
            for (int u = 0; u < 2; u++)
                psum[i][u] += __shfl_xor_sync(0xffffffffu, psum[i][u], o);
    }
    if ((lane & 3) == 0) {
        int rbase = mwarp + (lane >> 2);
#pragma unroll
        for (int i = 0; i < 2; i++)
#pragma unroll
            for (int u = 0; u < 2; u++)
                sumbuf[wc * 128 + rbase + i * 16 + u * 8] = psum[i][u];
    }
    __syncthreads();

    if (tid < 128) {
        g_partial[((size_t)b * 32 + blockIdx.x) * kN + m0 + tid] =
            sumbuf[tid] + sumbuf[128 + tid];
    }

    float* ab = attn + (size_t)b * kN * kN;
#pragma unroll
    for (int it = 0; it < 16; it++) {
        int r  = it * 8 + warp;
        int c4 = lane * 4;
        *(float4*)&ab[(size_t)(m0 + r) * kN + n0 + c4] =
            *(const float4*)&stg[r * kStgStride + c4];
    }
}

// ---------------------------------------------------------------------------
// Kernel 3: normalize rows using precomputed partials. REVERSED row order so
// first reads hit energy's still-L2-resident tail stores.
// ---------------------------------------------------------------------------
__global__ __launch_bounds__(256) void normalize_kernel(float* __restrict__ attn)
{
    __shared__ float s_inv;
    const int row = (kB * kN - 1) - blockIdx.x;   // reversed
    const int b   = row >> 12;
    const int m   = row & (kN - 1);
    const int tid = threadIdx.x;

    if (tid < 32) {
        float s = g_partial[((size_t)b * 32 + tid) * kN + m];
#pragma unroll
        for (int o = 16; o > 0; o >>= 1) s += __shfl_xor_sync(0xffffffffu, s, o);
        if (tid == 0) s_inv = 1.0f / s;
    }
    __syncthreads();
    const float inv = s_inv;

    float4* p = (float4*)(attn + (size_t)row * kN);
#pragma unroll
    for (int i = 0; i < 4; i++) {
        float4 v = p[tid + i * 256];
        v.x *= inv; v.y *= inv; v.z *= inv; v.w *= inv;
        p[tid + i * 256] = v;
    }
}

// ---------------------------------------------------------------------------
// Kernel 4: V projection (gamma != 0 only).
// ---------------------------------------------------------------------------
__global__ __launch_bounds__(256) void proj_v_kernel(
    const float* __restrict__ x,
    const float* __restrict__ wv, const float* __restrict__ bv,
    const float* __restrict__ gamma)
{
    if (*gamma == 0.0f) return;

    __shared__ __align__(16) float ys[16][64];
    __shared__ __align__(16) float ws[128][16];

    const int b   = blockIdx.z;
    const int ot  = blockIdx.y;
    const int n0  = blockIdx.x * 64;
    const int tid = threadIdx.x;
    const int n   = tid & 63;
    const int og  = tid >> 6;

    float acc[32];
#pragma unroll
    for (int j = 0; j < 32; j++) acc[j] = 0.f;

    const float* xb = x + (size_t)b * kC * kN;
    const float* wbase = wv + (size_t)(ot * 128) * kC;

    for (int c0 = 0; c0 < kC; c0 += 16) {
#pragma unroll
        for (int k = 0; k < 4; k++) {
            int cc = og + k * 4;
            ys[cc][n] = xb[(size_t)(c0 + cc) * kN + n0 + n];
        }
#pragma unroll
        for (int k = 0; k < 8; k++) {
            int l  = tid + k * 256;
            int o  = l >> 4;
            int cc = l & 15;
            ws[o][cc] = wbase[(size_t)o * kC + c0 + cc];
        }
        __syncthreads();

        float yr[16];
#pragma unroll
        for (int cc = 0; cc < 16; cc++) yr[cc] = ys[cc][n];

#pragma unroll
        for (int j = 0; j < 32; j++) {
            const float4* wr = (const float4*)ws[og * 32 + j];
            float4 w0 = wr[0], w1 = wr[1], w2 = wr[2], w3 = wr[3];
            float s = acc[j];
            s += w0.x * yr[0]  + w0.y * yr[1]  + w0.z * yr[2]  + w0.w * yr[3];
            s += w1.x * yr[4]  + w1.y * yr[5]  + w1.z * yr[6]  + w1.w * yr[7];
            s += w2.x * yr[8]  + w2.y * yr[9]  + w2.z * yr[10] + w2.w * yr[11];
            s += w3.x * yr[12] + w3.y * yr[13] + w3.z * yr[14] + w3.w * yr[15];
            acc[j] = s;
        }
        __syncthreads();
    }

    float* vb = g_v + (size_t)b * kC * kN;
#pragma unroll
    for (int j = 0; j < 32; j++) {
        int o = ot * 128 + og * 32 + j;
        vb[(size_t)o * kN + n0 + n] = acc[j] + bv[o];
    }
}

// ---------------------------------------------------------------------------
// Kernel 5: vout = v @ attn^T (gamma != 0 only)
// ---------------------------------------------------------------------------
__global__ __launch_bounds__(256) void bmm_kernel(
    const float* __restrict__ attn, const float* __restrict__ gamma)
{
    if (*gamma == 0.0f) return;

    __shared__ float vS[64][17];
    __shared__ float aS[64][17];

    const int b   = blockIdx.z;
    const int c0  = blockIdx.y * 64;
    const int m0  = blockIdx.x * 64;
    const int tid = threadIdx.x;
    const int tx  = tid & 15;
    const int ty  = tid >> 4;

    float acc[4][4];
#pragma unroll
    for (int i = 0; i < 4; i++)
#pragma unroll
        for (int j = 0; j < 4; j++) acc[i][j] = 0.f;

    const float* vb = g_v + (size_t)b * kC * kN;
    const float* ab = attn + (size_t)b * kN * kN;

    for (int nc = 0; nc < kN; nc += 16) {
#pragma unroll
        for (int k = 0; k < 4; k++) {
            int l = tid + k * 256;
            int r = l >> 4, cc = l & 15;
            vS[r][cc] = vb[(size_t)(c0 + r) * kN + nc + cc];
            aS[r][cc] = ab[(size_t)(m0 + r) * kN + nc + cc];
        }
        __syncthreads();
#pragma unroll
        for (int kk = 0; kk < 16; kk++) {
            float a[4], bb[4];
#pragma unroll
            for (int i = 0; i < 4; i++) a[i]  = vS[ty * 4 + i][kk];
#pragma unroll
            for (int j = 0; j < 4; j++) bb[j] = aS[tx * 4 + j][kk];
#pragma unroll
            for (int i = 0; i < 4; i++)
#pragma unroll
                for (int j = 0; j < 4; j++) acc[i][j] += a[i] * bb[j];
        }
        __syncthreads();
    }

#pragma unroll
    for (int i = 0; i < 4; i++)
#pragma unroll
        for (int j = 0; j < 4; j++)
            g_vout[((size_t)b * kC + c0 + ty * 4 + i) * kN + m0 + tx * 4 + j] = acc[i][j];
}

// ---------------------------------------------------------------------------
// Kernel 6: out = gamma * vout + x  (fast path gamma==0: pure copy)
// ---------------------------------------------------------------------------
__global__ __launch_bounds__(256) void final_kernel(
    const float* __restrict__ x, const float* __restrict__ gamma,
    float* __restrict__ out)
{
    const float g = *gamma;
    const size_t i = ((size_t)blockIdx.x * 256 + threadIdx.x) * 4;
    float4 xv = *(const float4*)&x[i];
    if (g != 0.f) {
        float4 a = *(const float4*)&g_vout[i];
        xv.x += g * a.x; xv.y += g * a.y; xv.z += g * a.z; xv.w += g * a.w;
    }
    *(float4*)&out[i] = xv;
}

// ---------------------------------------------------------------------------
extern "C" void kernel_launch(void* const* d_in, const int* in_sizes, int n_in,
                              void* d_out, int out_size)
{
    const float* x     = (const float*)d_in[0];
    const float* y     = (const float*)d_in[1];
    const float* wq    = (const float*)d_in[2];
    const float* bq    = (const float*)d_in[3];
    const float* wk    = (const float*)d_in[4];
    const float* bk    = (const float*)d_in[5];
    const float* wv    = (const float*)d_in[6];
    const float* bv    = (const float*)d_in[7];
    const float* gamma = (const float*)d_in[8];

    float* out  = (float*)d_out;
    float* attn = out + kOutElems;   // attention output region, [B][N][N]

    cudaFuncSetAttribute(energy_kernel,
                         cudaFuncAttributeMaxDynamicSharedMemorySize,
                         (int)kEnergySmem);
    cudaFuncSetAttribute(proj_qk_tc_kernel,
                         cudaFuncAttributeMaxDynamicSharedMemorySize,
                         (int)kProjSmem);

    proj_qk_tc_kernel<<<dim3(kN / 64, kB), 256, kProjSmem>>>(y, wq, bq, wk, bk);
    energy_kernel<<<dim3(kN / 128, kN / 128, kB), 256, kEnergySmem>>>(attn);
    normalize_kernel<<<kB * kN, 256>>>(attn);
    proj_v_kernel<<<dim3(kN / 64, 4, kB), 256>>>(x, wv, bv, gamma);
    bmm_kernel<<<dim3(kN / 64, kC / 64, kB), 256>>>(attn, gamma);
    final_kernel<<<(unsigned)(kOutElems / (256 * 4)), 256>>>(x, gamma, out);
}